// round 15
// baseline (speedup 1.0000x reference)
#include <cuda_runtime.h>
#include <cuda_bf16.h>

#define B_ 64
#define S_ 512
#define I_ 512
#define H_ 1024
#define O_ 512

// ---------------------------------------------------------------------------
// Static device scratch (no allocations anywhere).
// All bf16 operand arrays use the 8x8-tile-contiguous layout:
//   tile (r>>3, k>>3), 64 halves (128 B) per tile, row-major tiles.
// NOTE: only referenced from device code (host use = shadow-symbol bug, R9/R10).
// ---------------------------------------------------------------------------
__device__ float g_U[(S_ - 1) * B_ * H_];      // U[t][b][j]; reused as logits
__device__ float g_ht[B_ * H_];                // final hidden state (fp32)
__device__ __nv_bfloat16 g_hbf[2][2][B_ * H_]; // [buf][hi/lo] h tiled bf16
__device__ __nv_bfloat16 g_xhi[B_ * S_ * I_];  // x tiled per t: ((t*8+bt)*64+kt)
__device__ __nv_bfloat16 g_xlo[B_ * S_ * I_];
__device__ __nv_bfloat16 g_zhi[B_ * S_ * H_];  // Z rows r=b*512+t: ((r>>3)*128+kt)
__device__ __nv_bfloat16 g_zlo[B_ * S_ * H_];  // t=0 rows never written -> zero
__device__ __nv_bfloat16 g_wihi[H_ * I_];      // Wi tiled ((n>>3)*64+kt)
__device__ __nv_bfloat16 g_wilo[H_ * I_];
__device__ __nv_bfloat16 g_w3hi[O_ * H_];      // W3 tiled ((n>>3)*128+kt)
__device__ __nv_bfloat16 g_w3lo[O_ * H_];
__device__ unsigned g_bar4[4 * 32];            // per-bgroup barrier counters,
                                               // 128B apart (idx bg*32)

#define HTILE_IDX(b, j) ((((b) >> 3) * 128 + ((j) >> 3)) * 64 + (((b) & 7) << 3) + ((j) & 7))

// ---------------------------------------------------------------------------
// MMA / ldmatrix helpers (bf16, fp32 accum)
// ---------------------------------------------------------------------------
static __device__ __forceinline__ void ldsm_x2(unsigned& r0, unsigned& r1,
                                               unsigned addr) {
    asm volatile("ldmatrix.sync.aligned.m8n8.x2.shared.b16 {%0,%1}, [%2];"
                 : "=r"(r0), "=r"(r1) : "r"(addr));
}
static __device__ __forceinline__ void ldsm_x4(unsigned& r0, unsigned& r1,
                                               unsigned& r2, unsigned& r3,
                                               unsigned addr) {
    asm volatile("ldmatrix.sync.aligned.m8n8.x4.shared.b16 {%0,%1,%2,%3}, [%4];"
                 : "=r"(r0), "=r"(r1), "=r"(r2), "=r"(r3) : "r"(addr));
}
static __device__ __forceinline__ void mma16816(float* c, const unsigned* a,
                                                const unsigned* b) {
    asm volatile("mma.sync.aligned.m16n8k16.row.col.f32.bf16.bf16.f32 "
                 "{%0,%1,%2,%3}, {%4,%5,%6,%7}, {%8,%9}, {%0,%1,%2,%3};"
                 : "+f"(c[0]), "+f"(c[1]), "+f"(c[2]), "+f"(c[3])
                 : "r"(a[0]), "r"(a[1]), "r"(a[2]), "r"(a[3]),
                   "r"(b[0]), "r"(b[1]));
}
// L1-bypass 32-bit global load (h ping-pong is rewritten by other SMs)
static __device__ __forceinline__ unsigned ldcg(const void* p) {
    unsigned v;
    asm volatile("ld.global.cg.b32 %0, [%1];" : "=r"(v) : "l"(p));
    return v;
}

// fp32x4 -> hi/lo bf16x2 pairs written to (tiled) destinations
static __device__ __forceinline__ void cvt_pair(float4 v, __nv_bfloat16* hi,
                                                __nv_bfloat16* lo, long off) {
    __nv_bfloat162 h01 = __float22bfloat162_rn(make_float2(v.x, v.y));
    __nv_bfloat162 h23 = __float22bfloat162_rn(make_float2(v.z, v.w));
    float2 l01f = make_float2(v.x - __bfloat162float(h01.x),
                              v.y - __bfloat162float(h01.y));
    float2 l23f = make_float2(v.z - __bfloat162float(h23.x),
                              v.w - __bfloat162float(h23.y));
    *(__nv_bfloat162*)(hi + off)     = h01;
    *(__nv_bfloat162*)(hi + off + 2) = h23;
    *(__nv_bfloat162*)(lo + off)     = __float22bfloat162_rn(l01f);
    *(__nv_bfloat162*)(lo + off + 2) = __float22bfloat162_rn(l23f);
}

// ---------------------------------------------------------------------------
// Init + conversion kernels
// ---------------------------------------------------------------------------
__global__ void init_k(const float* __restrict__ h0) {
    int i = blockIdx.x * blockDim.x + threadIdx.x;
    if (i < B_ * H_) {
        int b = i >> 10, j = i & 1023;
        float v = h0[i];
        __nv_bfloat16 hi = __float2bfloat16(v);
        __nv_bfloat16 lo = __float2bfloat16(v - __bfloat162float(hi));
        int idx = HTILE_IDX(b, j);
        g_hbf[0][0][idx] = hi;
        g_hbf[0][1][idx] = lo;
    }
    if (i < 4 * 32) g_bar4[i] = 0u;
}

// x[b][t][k] -> per-t tiled: tile (t*8 + b>>3, k>>3)
__global__ void cvt_x_k(const float* __restrict__ x) {
    long i4 = (long)blockIdx.x * blockDim.x + threadIdx.x;
    if (i4 >= (long)B_ * S_ * I_ / 4) return;
    long e = i4 << 2;
    int b = (int)(e >> 18);
    int rem = (int)(e & 262143);
    int t = rem >> 9;
    int k = rem & 511;
    float4 v = *(const float4*)&x[e];
    long off = ((long)((t << 3) + (b >> 3)) * 64 + (k >> 3)) * 64
             + ((b & 7) << 3) + (k & 7);
    cvt_pair(v, g_xhi, g_xlo, off);
}

// W[n][k] (NR x NC) -> tiled; WHICH selects destination (device-side!)
template <int NR, int NC, int WHICH>
__global__ void cvt_w_k(const float* __restrict__ W) {
    __nv_bfloat16* hi = (WHICH == 0) ? g_wihi : g_w3hi;
    __nv_bfloat16* lo = (WHICH == 0) ? g_wilo : g_w3lo;
    int i4 = blockIdx.x * blockDim.x + threadIdx.x;
    if (i4 >= NR * NC / 4) return;
    int e = i4 << 2;
    int n = e / NC, k = e % NC;
    float4 v = *(const float4*)&W[e];
    long off = ((long)(n >> 3) * (NC / 8) + (k >> 3)) * 64 + ((n & 7) << 3) + (k & 7);
    cvt_pair(v, hi, lo, off);
}

// ---------------------------------------------------------------------------
// gemm0: pure-bf16 tensor GEMM, 64x64 CTA tile, K-chunk 32 (R13 version).
//   U = x_t @ Wi^T + bi   (A = g_x*, W = g_wi*, K=512, N=1024)
// ---------------------------------------------------------------------------
__global__ __launch_bounds__(256) void gemm0_bf(const float* __restrict__ bias) {
    constexpr int K = I_;
    constexpr int N = H_;
    constexpr int NCHUNK = K / 32;
    constexpr int KT = K / 8;

    const __nv_bfloat16* Ahi = g_xhi;
    const __nv_bfloat16* Alo = g_xlo;
    const __nv_bfloat16* Whi = g_wihi;
    const __nv_bfloat16* Wlo = g_wilo;

    __shared__ __align__(16) __nv_bfloat16 sbuf[2][8192];

    const int tid  = threadIdx.x;
    const int lane = tid & 31;
    const int wid  = tid >> 5;
    const int wm   = wid & 1;
    const int wn   = wid >> 1;
    const int n0   = blockIdx.x * 64;
    const int y    = blockIdx.y;

    const unsigned sbase = (unsigned)__cvta_generic_to_shared(&sbuf[0][0]);

    auto stage = [&](int c, int bufp) {
#pragma unroll
        for (int e = 0; e < 4; ++e) {
            int ci = tid + (e << 8);
            int a  = ci >> 8;
            int tl = (ci & 255) >> 3;
            int bt = tl >> 2, ktl = tl & 3;
            int kt = (c << 2) + ktl;
            int inner = (ci & 7) << 4;
            long tileIdx = (a < 2) ? ((long)((y << 3) + bt) * KT + kt)
                                   : ((long)((n0 >> 3) + bt) * KT + kt);
            const __nv_bfloat16* src =
                (a == 0 ? Ahi : a == 1 ? Alo : a == 2 ? Whi : Wlo);
            const char* gsrc = (const char*)src + tileIdx * 128 + inner;
            unsigned dst = sbase + (unsigned)(bufp * 16384 + a * 4096 + tl * 128 + inner);
            asm volatile("cp.async.cg.shared.global [%0], [%1], 16;"
                         :: "r"(dst), "l"(gsrc));
        }
    };

    float acc[2][2][4];
#pragma unroll
    for (int i = 0; i < 2; ++i)
#pragma unroll
        for (int j = 0; j < 2; ++j)
#pragma unroll
            for (int q = 0; q < 4; ++q) acc[i][j][q] = 0.f;

    const int g4   = lane >> 3;
    const int g2   = g4 & 1;
    const int rowi = (lane & 7) << 4;

    stage(0, 0);
    asm volatile("cp.async.commit_group;");

    for (int c = 0; c < NCHUNK; ++c) {
        const int cur = c & 1;
        if (c + 1 < NCHUNK) {
            stage(c + 1, cur ^ 1);
            asm volatile("cp.async.commit_group;");
            asm volatile("cp.async.wait_group 1;" ::: "memory");
        } else {
            asm volatile("cp.async.wait_group 0;" ::: "memory");
        }
        __syncthreads();

        const unsigned bA0 = sbase + (unsigned)(cur * 16384);
        const unsigned bA1 = bA0 + 4096;
        const unsigned bW0 = bA0 + 8192;
        const unsigned bW1 = bA0 + 12288;

#pragma unroll
        for (int ks = 0; ks < 2; ++ks) {
            unsigned ahi[2][4], alo[2][4], bhi[2][2], blo[2][2];
#pragma unroll
            for (int mf = 0; mf < 2; ++mf) {
                int mi = wm * 4 + mf * 2;
                unsigned ti  = (unsigned)((mi + (g4 & 1)) * 4 + (ks << 1) + (g4 >> 1));
                unsigned off = ti * 128u + rowi;
                ldsm_x4(ahi[mf][0], ahi[mf][1], ahi[mf][2], ahi[mf][3], bA0 + off);
                ldsm_x4(alo[mf][0], alo[mf][1], alo[mf][2], alo[mf][3], bA1 + off);
            }
#pragma unroll
            for (int nf = 0; nf < 2; ++nf) {
                int ni = wn * 2 + nf;
                unsigned ti  = (unsigned)(ni * 4 + (ks << 1) + g2);
                unsigned off = ti * 128u + rowi;
                ldsm_x2(bhi[nf][0], bhi[nf][1], bW0 + off);
                ldsm_x2(blo[nf][0], blo[nf][1], bW1 + off);
            }
#pragma unroll
            for (int mf = 0; mf < 2; ++mf)
#pragma unroll
                for (int nf = 0; nf < 2; ++nf) {
                    mma16816(acc[mf][nf], ahi[mf], bhi[nf]);
                    mma16816(acc[mf][nf], ahi[mf], blo[nf]);
                    mma16816(acc[mf][nf], alo[mf], bhi[nf]);
                }
        }
        __syncthreads();
    }

#pragma unroll
    for (int nf = 0; nf < 2; ++nf) {
        int bcol = n0 + wn * 16 + nf * 8 + ((lane & 3) << 1);
        float2 bv = *(const float2*)&bias[bcol];
#pragma unroll
        for (int mf = 0; mf < 2; ++mf) {
            long r0 = (long)(y << 6) + wm * 32 + mf * 16 + (lane >> 2);
            float2 o0 = make_float2(acc[mf][nf][0] + bv.x, acc[mf][nf][1] + bv.y);
            float2 o1 = make_float2(acc[mf][nf][2] + bv.x, acc[mf][nf][3] + bv.y);
            *(float2*)&g_U[r0 * N + bcol]       = o0;
            *(float2*)&g_U[(r0 + 8) * N + bcol] = o1;
        }
    }
}

// ---------------------------------------------------------------------------
// gemm1: 128x64 CTA tile (2 row-blocks share staged W -> half W L2 traffic,
// double the MMAs per sync). K-chunk 32, 8 warps = 4m(32 rows) x 2n(32 cols),
// warp tile 32x32 = 2 mf x 4 nf. SMEM: 24KB/buffer (A 16KB + W 8KB), x2.
//   logits = Z @ W3^T + b3   (A = g_z*, W = g_w3*, K=1024, N=512)
// ---------------------------------------------------------------------------
__global__ __launch_bounds__(256) void gemm1_bf(const float* __restrict__ bias) {
    constexpr int K = H_;
    constexpr int N = O_;
    constexpr int NCHUNK = K / 32;   // 32
    constexpr int KT = K / 8;        // 128

    __shared__ __align__(16) __nv_bfloat16 sbuf[2][12288];   // 24KB each

    const int tid  = threadIdx.x;
    const int lane = tid & 31;
    const int wid  = tid >> 5;
    const int wm   = wid & 3;        // 4 m-blocks of 32 rows
    const int wn   = wid >> 2;       // 2 n-blocks of 32 cols
    const int n0   = blockIdx.x * 64;
    const int y    = blockIdx.y;     // 128-row block (0..255)

    const unsigned sbase = (unsigned)__cvta_generic_to_shared(&sbuf[0][0]);

    // stage one 32-k chunk: 192 tiles = 1536 x 16B cp.asyncs (6 per thread)
    // tile order: Ahi[0..63] Alo[64..127] Whi[128..159] Wlo[160..191]
    auto stage = [&](int c, int bufp) {
#pragma unroll
        for (int e = 0; e < 6; ++e) {
            int ci = tid + (e << 8);          // 0..1535
            int tl = ci >> 3;                 // global tile 0..191
            int inner = (ci & 7) << 4;
            const __nv_bfloat16* src;
            long tileIdx;
            if (tl < 128) {                   // A: 16 row-tiles x 4 k-tiles
                int local = tl & 63;
                int bt = local >> 2, ktl = local & 3;
                tileIdx = (long)((y << 4) + bt) * KT + (c << 2) + ktl;
                src = (tl < 64) ? g_zhi : g_zlo;
            } else {                          // W: 8 n-tiles x 4 k-tiles
                int local = tl & 31;
                int bt = local >> 2, ktl = local & 3;
                tileIdx = (long)((n0 >> 3) + bt) * KT + (c << 2) + ktl;
                src = (tl < 160) ? g_w3hi : g_w3lo;
            }
            const char* gsrc = (const char*)src + tileIdx * 128 + inner;
            unsigned dst = sbase + (unsigned)(bufp * 24576 + tl * 128 + inner);
            asm volatile("cp.async.cg.shared.global [%0], [%1], 16;"
                         :: "r"(dst), "l"(gsrc));
        }
    };

    float acc[2][4][4];
#pragma unroll
    for (int i = 0; i < 2; ++i)
#pragma unroll
        for (int j = 0; j < 4; ++j)
#pragma unroll
            for (int q = 0; q < 4; ++q) acc[i][j][q] = 0.f;

    const int g4   = lane >> 3;
    const int g2   = g4 & 1;
    const int rowi = (lane & 7) << 4;

    stage(0, 0);
    asm volatile("cp.async.commit_group;");

    for (int c = 0; c < NCHUNK; ++c) {
        const int cur = c & 1;
        if (c + 1 < NCHUNK) {
            stage(c + 1, cur ^ 1);
            asm volatile("cp.async.commit_group;");
            asm volatile("cp.async.wait_group 1;" ::: "memory");
        } else {
            asm volatile("cp.async.wait_group 0;" ::: "memory");
        }
        __syncthreads();

        const unsigned bA0 = sbase + (unsigned)(cur * 24576);
        const unsigned bA1 = bA0 + 8192;
        const unsigned bW0 = bA0 + 16384;
        const unsigned bW1 = bA0 + 20480;

#pragma unroll
        for (int ks = 0; ks < 2; ++ks) {
            unsigned ahi[2][4], alo[2][4], bhi[4][2], blo[4][2];
#pragma unroll
            for (int mf = 0; mf < 2; ++mf) {
                int mi = wm * 4 + mf * 2;     // first row-tile of 16-row block
                unsigned ti  = (unsigned)((mi + (g4 & 1)) * 4 + (ks << 1) + (g4 >> 1));
                unsigned off = ti * 128u + rowi;
                ldsm_x4(ahi[mf][0], ahi[mf][1], ahi[mf][2], ahi[mf][3], bA0 + off);
                ldsm_x4(alo[mf][0], alo[mf][1], alo[mf][2], alo[mf][3], bA1 + off);
            }
#pragma unroll
            for (int nf = 0; nf < 4; ++nf) {
                int ni = wn * 4 + nf;         // 8-col n-tile index (0..7)
                unsigned ti  = (unsigned)(ni * 4 + (ks << 1) + g2);
                unsigned off = ti * 128u + rowi;
                ldsm_x2(bhi[nf][0], bhi[nf][1], bW0 + off);
                ldsm_x2(blo[nf][0], blo[nf][1], bW1 + off);
            }
#pragma unroll
            for (int mf = 0; mf < 2; ++mf)
#pragma unroll
                for (int nf = 0; nf < 4; ++nf) {
                    mma16816(acc[mf][nf], ahi[mf], bhi[nf]);
                    mma16816(acc[mf][nf], ahi[mf], blo[nf]);
                    mma16816(acc[mf][nf], alo[mf], bhi[nf]);
                }
        }
        __syncthreads();
    }

#pragma unroll
    for (int nf = 0; nf < 4; ++nf) {
        int bcol = n0 + wn * 32 + nf * 8 + ((lane & 3) << 1);
        float2 bv = *(const float2*)&bias[bcol];
#pragma unroll
        for (int mf = 0; mf < 2; ++mf) {
            long r0 = (long)(y << 7) + wm * 32 + mf * 16 + (lane >> 2);
            float2 o0 = make_float2(acc[mf][nf][0] + bv.x, acc[mf][nf][1] + bv.y);
            float2 o1 = make_float2(acc[mf][nf][2] + bv.x, acc[mf][nf][3] + bv.y);
            *(float2*)&g_U[r0 * N + bcol]       = o0;
            *(float2*)&g_U[(r0 + 8) * N + bcol] = o1;
        }
    }
}

// ---------------------------------------------------------------------------
// Persistent recurrence kernel v11 (R13, measured win) — tensor cores,
// direct-from-global A fragments, Wh B-fragments in registers, U prefetch in
// barrier window, per-bgroup barriers with fused release-atomic.
// ---------------------------------------------------------------------------
#define PSTRIDE 34
#define RECUR_SMEM (16384 * 2 * 2 + 16 * 16 * PSTRIDE * 4)

__global__ void __launch_bounds__(512, 1) recur_k(const float* __restrict__ Wh,
                                                  const float* __restrict__ bh) {
    extern __shared__ char smraw[];
    __nv_bfloat16* hsH = (__nv_bfloat16*)smraw;          // setup temp only
    float* part = (float*)(smraw + 65536);               // [16][16][PSTRIDE]

    const int tid = threadIdx.x;
    const int w   = tid >> 5;            // warp 0..15 -> k slice [w*64, +64)
    const int l   = tid & 31;
    const int cb  = blockIdx.x;
    const int j0  = (cb & 31) << 5;
    const int bg  = cb >> 5;
    const int b0  = bg << 4;
    const int j   = j0 + l;
    unsigned* bar = &g_bar4[bg << 5];    // this group's padded counter

    const unsigned baseW = (unsigned)__cvta_generic_to_shared(hsH);

    // ---- setup: Wh -> split-bf16 B fragments in registers (two passes) ----
    unsigned Bhi[4][4][2], Blo[4][4][2];
    {
        __nv_bfloat16* wtmp = hsH;
#pragma unroll 1
        for (int pass = 0; pass < 2; ++pass) {
#pragma unroll 1
            for (int it = 0; it < 16; ++it) {
                int e  = tid + (it << 9);
                int jj = e >> 8;
                int k  = (e & 255) << 2;
                float4 f = *(const float4*)&Wh[(long)(j0 + jj) * H_ + k];
                __nv_bfloat162 p01, p23;
                if (pass == 0) {
                    p01 = __float22bfloat162_rn(make_float2(f.x, f.y));
                    p23 = __float22bfloat162_rn(make_float2(f.z, f.w));
                } else {
                    __nv_bfloat162 h01 = __float22bfloat162_rn(make_float2(f.x, f.y));
                    __nv_bfloat162 h23 = __float22bfloat162_rn(make_float2(f.z, f.w));
                    p01 = __float22bfloat162_rn(make_float2(
                        f.x - __bfloat162float(h01.x), f.y - __bfloat162float(h01.y)));
                    p23 = __float22bfloat162_rn(make_float2(
                        f.z - __bfloat162float(h23.x), f.w - __bfloat162float(h23.y)));
                }
                int off = ((jj >> 3) * 128 + (k >> 3)) * 64 + ((jj & 7) << 3) + (k & 7);
                *(__nv_bfloat162*)(wtmp + off)     = p01;
                *(__nv_bfloat162*)(wtmp + off + 2) = p23;
            }
            __syncthreads();
#pragma unroll
            for (int s = 0; s < 4; ++s) {
                int kt0 = (w << 3) + (s << 1);
#pragma unroll
                for (int nt = 0; nt < 4; ++nt) {
                    unsigned addr = baseW +
                        (unsigned)(((nt * 128 + kt0 + ((l >> 3) & 1)) << 7) + ((l & 7) << 4));
                    if (pass == 0) ldsm_x2(Bhi[s][nt][0], Bhi[s][nt][1], addr);
                    else           ldsm_x2(Blo[s][nt][0], Blo[s][nt][1], addr);
                }
            }
            __syncthreads();
        }
    }

    const int rb = tid >> 5;
    const int gb = b0 + rb;
    const float bhj = bh[j];
    const int inner = ((l >> 2) << 4) + ((l & 3) << 2);   // frag byte in tile

    // U prefetch for step 0
    float u_next = g_U[(long)(0 * 64 + gb) * H_ + j];

    for (int m = 0; m < S_; ++m) {
        const char* hH = (const char*)(g_hbf[m & 1][0] + (bg << 14));
        const char* hL = (const char*)(g_hbf[m & 1][1] + (bg << 14));

        auto loadfrag = [&](int s, unsigned* aH, unsigned* aL) {
            int kt = (w << 3) + (s << 1);
            int o00 = (kt << 7) + inner;      // bt0, kt
            int o10 = o00 + 16384;            // bt1, kt
            aH[0] = ldcg(hH + o00); aH[1] = ldcg(hH + o10);
            aH[2] = ldcg(hH + o00 + 128); aH[3] = ldcg(hH + o10 + 128);
            aL[0] = ldcg(hL + o00); aL[1] = ldcg(hL + o10);
            aL[2] = ldcg(hL + o00 + 128); aL[3] = ldcg(hL + o10 + 128);
        };

        const float u0 = u_next;   // valid when m <= S_-2

        float acc[4][4];
#pragma unroll
        for (int nt = 0; nt < 4; ++nt)
#pragma unroll
            for (int q = 0; q < 4; ++q) acc[nt][q] = 0.f;

        unsigned aH[2][4], aL[2][4];
        loadfrag(0, aH[0], aL[0]);
#pragma unroll
        for (int s = 0; s < 4; ++s) {
            const int cur = s & 1;
            if (s < 3) loadfrag(s + 1, aH[cur ^ 1], aL[cur ^ 1]);
#pragma unroll
            for (int nt = 0; nt < 4; ++nt) {
                mma16816(acc[nt], aH[cur], Bhi[s][nt]);
                mma16816(acc[nt], aH[cur], Blo[s][nt]);
                mma16816(acc[nt], aL[cur], Bhi[s][nt]);
            }
        }

        // ---- store partials (padded stride -> conflict-free) ----
        {
            float* pw = part + w * (16 * PSTRIDE);
            int prow = l >> 2, pcol = (l & 3) << 1;
#pragma unroll
            for (int nt = 0; nt < 4; ++nt) {
                *(float2*)&pw[prow * PSTRIDE + nt * 8 + pcol] =
                    make_float2(acc[nt][0], acc[nt][1]);
                *(float2*)&pw[(prow + 8) * PSTRIDE + nt * 8 + pcol] =
                    make_float2(acc[nt][2], acc[nt][3]);
            }
        }
        __syncthreads();

        // ---- reduce 16 k-slices, bias, tanh, h write (bf16 hi/lo) ----
        float av;
        {
            float s = 0.f;
#pragma unroll
            for (int ww = 0; ww < 16; ++ww)
                s += part[ww * (16 * PSTRIDE) + rb * PSTRIDE + l];
            av = s + bhj;
            if (m <= S_ - 2) {
                float hv = tanhf(u0 + av);
                __nv_bfloat16 hi = __float2bfloat16(hv);
                __nv_bfloat16 lo = __float2bfloat16(hv - __bfloat162float(hi));
                int idx = HTILE_IDX(gb, j);
                g_hbf[(m + 1) & 1][0][idx] = hi;
                g_hbf[(m + 1) & 1][1][idx] = lo;
                if (m == S_ - 2) g_ht[gb * H_ + j] = hv;
            }
        }

        // z write target (tiled bf16, rows r = b*512 + t)
        const int zr = (gb << 9) + m;
        const long zt = ((long)(zr >> 3) * 128 + (j >> 3)) * 64
                      + ((zr & 7) << 3) + (j & 7);

        if (m != S_ - 1) {
            __syncthreads();
            if (tid == 0) {
                asm volatile("red.release.gpu.global.add.u32 [%0], %1;"
                             :: "l"(bar), "r"(1u) : "memory");
            }
            // barrier window: z tanh + bf16 store AND next-step U prefetch
            if (m >= 1) {
                float zv = tanhf(av);
                __nv_bfloat16 zh = __float2bfloat16(zv);
                g_zhi[zt] = zh;
                g_zlo[zt] = __float2bfloat16(zv - __bfloat162float(zh));
            }
            if (m + 1 <= S_ - 2)
                u_next = g_U[((long)(m + 1) * 64 + gb) * H_ + j];
            if (tid == 0) {
                unsigned target = (unsigned)(32 * (m + 1));
                unsigned v;
                do {
                    asm volatile("ld.acquire.gpu.global.u32 %0, [%1];"
                                 : "=r"(v) : "l"(bar));
                } while (v < target);
            }
            __syncthreads();
        } else {
            float zv = tanhf(av);
            __nv_bfloat16 zh = __float2bfloat16(zv);
            g_zhi[zt] = zh;
            g_zlo[zt] = __float2bfloat16(zv - __bfloat162float(zh));
        }
    }
}

// ---------------------------------------------------------------------------
// Row softmax over O_=512 cols; warp per row, logits read from g_U (reused).
// ---------------------------------------------------------------------------
__global__ __launch_bounds__(256) void softmax_k(float* __restrict__ out) {
    int r = blockIdx.x * 8 + (threadIdx.x >> 5);
    int l = threadIdx.x & 31;
    const float* row = g_U + (long)r * O_;

    float4 v[4];
    float mx = -3.0e38f;
#pragma unroll
    for (int q = 0; q < 4; ++q) {
        v[q] = *(const float4*)&row[(l + (q << 5)) << 2];
        mx = fmaxf(mx, fmaxf(fmaxf(v[q].x, v[q].y), fmaxf(v[q].z, v[q].w)));
    }
#pragma unroll
    for (int o = 16; o; o >>= 1) mx = fmaxf(mx, __shfl_xor_sync(~0u, mx, o));

    float s = 0.f;
#pragma unroll
    for (int q = 0; q < 4; ++q) {
        v[q].x = expf(v[q].x - mx); v[q].y = expf(v[q].y - mx);
        v[q].z = expf(v[q].z - mx); v[q].w = expf(v[q].w - mx);
        s += (v[q].x + v[q].y) + (v[q].z + v[q].w);
    }
#pragma unroll
    for (int o = 16; o; o >>= 1) s += __shfl_xor_sync(~0u, s, o);
    float inv = 1.0f / s;

#pragma unroll
    for (int q = 0; q < 4; ++q) {
        float4 wv = make_float4(v[q].x * inv, v[q].y * inv, v[q].z * inv, v[q].w * inv);
        *(float4*)&out[(long)r * O_ + ((l + (q << 5)) << 2)] = wv;
    }
}

__global__ void copyht_k(float* __restrict__ dst) {
    int i = blockIdx.x * blockDim.x + threadIdx.x;
    if (i < B_ * H_) dst[i] = g_ht[i];
}

// ---------------------------------------------------------------------------
// Launch (only harness pointers cross the host/device boundary)
// ---------------------------------------------------------------------------
extern "C" void kernel_launch(void* const* d_in, const int* in_sizes, int n_in,
                              void* d_out, int out_size) {
    const float* x  = (const float*)d_in[0];
    const float* h0 = (const float*)d_in[1];
    const float* Wi = (const float*)d_in[2];
    const float* bi = (const float*)d_in[3];
    const float* Wh = (const float*)d_in[4];
    const float* bh = (const float*)d_in[5];
    const float* W3 = (const float*)d_in[6];
    const float* b3 = (const float*)d_in[7];
    float* out = (float*)d_out;

    cudaFuncSetAttribute(recur_k, cudaFuncAttributeMaxDynamicSharedMemorySize,
                         RECUR_SMEM);

    // 1. init state + pre-convert operands to tiled bf16 hi/lo
    init_k<<<(B_ * H_ + 255) / 256, 256>>>(h0);
    cvt_x_k<<<(B_ * S_ * I_ / 4 + 255) / 256, 256>>>(x);
    cvt_w_k<H_, I_, 0><<<(H_ * I_ / 4 + 255) / 256, 256>>>(Wi);
    cvt_w_k<O_, H_, 1><<<(O_ * H_ / 4 + 255) / 256, 256>>>(W3);

    // 2. U[t][b][:] = x[b][t][:] @ Wi^T + bi   (t = 0..510)
    gemm0_bf<<<dim3(H_ / 64, S_ - 1), 256>>>(bi);

    // 3. Serial recurrence (persistent, 128 CTAs, 512 steps, tensor cores)
    recur_k<<<128, 512, RECUR_SMEM>>>(Wh, bh);

    // 4. logits = Z @ W3^T + b3   (128-row tiles; g_U reused as logits)
    gemm1_bf<<<dim3(O_ / 64, (B_ * S_) / 128), 256>>>(b3);

    // 5. softmax -> d_out
    softmax_k<<<(B_ * S_) / 8, 256>>>(out);

    // 6. final hidden state appended after softmax output
    if (out_size >= B_ * S_ * O_ + B_ * H_) {
        copyht_k<<<(B_ * H_ + 255) / 256, 256>>>(out + (long)B_ * S_ * O_);
    }
}

// round 16
// speedup vs baseline: 1.0037x; 1.0037x over previous
#include <cuda_runtime.h>
#include <cuda_bf16.h>

#define B_ 64
#define S_ 512
#define I_ 512
#define H_ 1024
#define O_ 512

// ---------------------------------------------------------------------------
// Static device scratch (no allocations anywhere).
// All bf16 operand arrays use the 8x8-tile-contiguous layout:
//   tile (r>>3, k>>3), 64 halves (128 B) per tile, row-major tiles.
// NOTE: only referenced from device code (host use = shadow-symbol bug, R9/R10).
// ---------------------------------------------------------------------------
__device__ float g_U[(S_ - 1) * B_ * H_];      // U[t][b][j]; reused as logits
__device__ float g_ht[B_ * H_];                // final hidden state (fp32)
__device__ __nv_bfloat16 g_hbf[2][2][B_ * H_]; // [buf][hi/lo] h tiled bf16
__device__ __nv_bfloat16 g_xhi[B_ * S_ * I_];  // x tiled per t: ((t*8+bt)*64+kt)
__device__ __nv_bfloat16 g_xlo[B_ * S_ * I_];
__device__ __nv_bfloat16 g_zhi[B_ * S_ * H_];  // Z rows r=b*512+t: ((r>>3)*128+kt)
__device__ __nv_bfloat16 g_zlo[B_ * S_ * H_];  // t=0 rows never written -> zero
__device__ __nv_bfloat16 g_wihi[H_ * I_];      // Wi tiled ((n>>3)*64+kt)
__device__ __nv_bfloat16 g_wilo[H_ * I_];
__device__ __nv_bfloat16 g_w3hi[O_ * H_];      // W3 tiled ((n>>3)*128+kt)
__device__ __nv_bfloat16 g_w3lo[O_ * H_];
__device__ unsigned g_bar4[4 * 32];            // per-bgroup barrier counters,
                                               // 128B apart (idx bg*32)

#define HTILE_IDX(b, j) ((((b) >> 3) * 128 + ((j) >> 3)) * 64 + (((b) & 7) << 3) + ((j) & 7))

// ---------------------------------------------------------------------------
// MMA / ldmatrix helpers (bf16, fp32 accum)
// ---------------------------------------------------------------------------
static __device__ __forceinline__ void ldsm_x2(unsigned& r0, unsigned& r1,
                                               unsigned addr) {
    asm volatile("ldmatrix.sync.aligned.m8n8.x2.shared.b16 {%0,%1}, [%2];"
                 : "=r"(r0), "=r"(r1) : "r"(addr));
}
static __device__ __forceinline__ void ldsm_x4(unsigned& r0, unsigned& r1,
                                               unsigned& r2, unsigned& r3,
                                               unsigned addr) {
    asm volatile("ldmatrix.sync.aligned.m8n8.x4.shared.b16 {%0,%1,%2,%3}, [%4];"
                 : "=r"(r0), "=r"(r1), "=r"(r2), "=r"(r3) : "r"(addr));
}
static __device__ __forceinline__ void mma16816(float* c, const unsigned* a,
                                                const unsigned* b) {
    asm volatile("mma.sync.aligned.m16n8k16.row.col.f32.bf16.bf16.f32 "
                 "{%0,%1,%2,%3}, {%4,%5,%6,%7}, {%8,%9}, {%0,%1,%2,%3};"
                 : "+f"(c[0]), "+f"(c[1]), "+f"(c[2]), "+f"(c[3])
                 : "r"(a[0]), "r"(a[1]), "r"(a[2]), "r"(a[3]),
                   "r"(b[0]), "r"(b[1]));
}
// L1-bypass 32-bit global load (h ping-pong is rewritten by other SMs)
static __device__ __forceinline__ unsigned ldcg(const void* p) {
    unsigned v;
    asm volatile("ld.global.cg.b32 %0, [%1];" : "=r"(v) : "l"(p));
    return v;
}

// fp32x4 -> hi/lo bf16x2 pairs written to (tiled) destinations
static __device__ __forceinline__ void cvt_pair(float4 v, __nv_bfloat16* hi,
                                                __nv_bfloat16* lo, long off) {
    __nv_bfloat162 h01 = __float22bfloat162_rn(make_float2(v.x, v.y));
    __nv_bfloat162 h23 = __float22bfloat162_rn(make_float2(v.z, v.w));
    float2 l01f = make_float2(v.x - __bfloat162float(h01.x),
                              v.y - __bfloat162float(h01.y));
    float2 l23f = make_float2(v.z - __bfloat162float(h23.x),
                              v.w - __bfloat162float(h23.y));
    *(__nv_bfloat162*)(hi + off)     = h01;
    *(__nv_bfloat162*)(hi + off + 2) = h23;
    *(__nv_bfloat162*)(lo + off)     = __float22bfloat162_rn(l01f);
    *(__nv_bfloat162*)(lo + off + 2) = __float22bfloat162_rn(l23f);
}

// ---------------------------------------------------------------------------
// FUSED prep kernel: one launch does all independent setup work, partitioned
// by linear float4 index:
//   [0, XN)              cvt x   -> g_xhi/g_xlo (per-t tiled)
//   [XN, XN+WIN)         cvt Wi  -> g_wihi/g_wilo
//   [.., +W3N)           cvt W3  -> g_w3hi/g_w3lo
//   [.., +HN)            h0      -> g_hbf[0] (tiled bf16 hi/lo)
//   [.., +128)           barrier counters reset
// ---------------------------------------------------------------------------
#define XN  (B_ * S_ * I_ / 4)
#define WIN (H_ * I_ / 4)
#define W3N (O_ * H_ / 4)
#define HN  (B_ * H_ / 4)
#define PREP_TOTAL (XN + WIN + W3N + HN + 128)

__global__ void prep_k(const float* __restrict__ x, const float* __restrict__ Wi,
                       const float* __restrict__ W3, const float* __restrict__ h0) {
    long idx = (long)blockIdx.x * blockDim.x + threadIdx.x;
    if (idx >= PREP_TOTAL) return;

    if (idx < XN) {
        long e = idx << 2;
        int b = (int)(e >> 18);
        int rem = (int)(e & 262143);
        int t = rem >> 9;
        int k = rem & 511;
        float4 v = *(const float4*)&x[e];
        long off = ((long)((t << 3) + (b >> 3)) * 64 + (k >> 3)) * 64
                 + ((b & 7) << 3) + (k & 7);
        cvt_pair(v, g_xhi, g_xlo, off);
    } else if (idx < XN + WIN) {
        int e = (int)(idx - XN) << 2;
        int n = e / I_, k = e % I_;
        float4 v = *(const float4*)&Wi[e];
        long off = ((long)(n >> 3) * (I_ / 8) + (k >> 3)) * 64 + ((n & 7) << 3) + (k & 7);
        cvt_pair(v, g_wihi, g_wilo, off);
    } else if (idx < XN + WIN + W3N) {
        int e = (int)(idx - XN - WIN) << 2;
        int n = e / H_, k = e % H_;
        float4 v = *(const float4*)&W3[e];
        long off = ((long)(n >> 3) * (H_ / 8) + (k >> 3)) * 64 + ((n & 7) << 3) + (k & 7);
        cvt_pair(v, g_w3hi, g_w3lo, off);
    } else if (idx < XN + WIN + W3N + HN) {
        int e = (int)(idx - XN - WIN - W3N) << 2;   // 4 consecutive h elems
        int b = e >> 10, j = e & 1023;              // j..j+3 same tile group
        float4 v = *(const float4*)&h0[e];
        long off = HTILE_IDX(b, j);                 // (j&7)%4==0 -> contiguous
        cvt_pair(v, g_hbf[0][0], g_hbf[0][1], off);
    } else {
        g_bar4[idx - (XN + WIN + W3N + HN)] = 0u;
    }
}

// ---------------------------------------------------------------------------
// Pure-bf16 tensor GEMM, 64x64 CTA tile, K-chunk 32 (exact R13 version —
// measured best). Operands selected by MODE in device code.
//   MODE 0: U = x_t @ Wi^T + bi   (A = g_x*, W = g_wi*, K=512,  N=1024)
//   MODE 1: logits = Z @ W3^T+b3  (A = g_z*, W = g_w3*, K=1024, N=512)
// ---------------------------------------------------------------------------
template <int MODE>
__global__ __launch_bounds__(256) void gemm_bf(const float* __restrict__ bias) {
    constexpr int K = (MODE == 0) ? I_ : H_;
    constexpr int N = (MODE == 0) ? H_ : O_;
    constexpr int NCHUNK = K / 32;
    constexpr int KT = K / 8;

    const __nv_bfloat16* Ahi = (MODE == 0) ? g_xhi : g_zhi;
    const __nv_bfloat16* Alo = (MODE == 0) ? g_xlo : g_zlo;
    const __nv_bfloat16* Whi = (MODE == 0) ? g_wihi : g_w3hi;
    const __nv_bfloat16* Wlo = (MODE == 0) ? g_wilo : g_w3lo;

    __shared__ __align__(16) __nv_bfloat16 sbuf[2][8192];

    const int tid  = threadIdx.x;
    const int lane = tid & 31;
    const int wid  = tid >> 5;
    const int wm   = wid & 1;
    const int wn   = wid >> 1;
    const int n0   = blockIdx.x * 64;
    const int y    = blockIdx.y;

    const unsigned sbase = (unsigned)__cvta_generic_to_shared(&sbuf[0][0]);

    auto stage = [&](int c, int bufp) {
#pragma unroll
        for (int e = 0; e < 4; ++e) {
            int ci = tid + (e << 8);
            int a  = ci >> 8;
            int tl = (ci & 255) >> 3;
            int bt = tl >> 2, ktl = tl & 3;
            int kt = (c << 2) + ktl;
            int inner = (ci & 7) << 4;
            long tileIdx = (a < 2) ? ((long)((y << 3) + bt) * KT + kt)
                                   : ((long)((n0 >> 3) + bt) * KT + kt);
            const __nv_bfloat16* src =
                (a == 0 ? Ahi : a == 1 ? Alo : a == 2 ? Whi : Wlo);
            const char* gsrc = (const char*)src + tileIdx * 128 + inner;
            unsigned dst = sbase + (unsigned)(bufp * 16384 + a * 4096 + tl * 128 + inner);
            asm volatile("cp.async.cg.shared.global [%0], [%1], 16;"
                         :: "r"(dst), "l"(gsrc));
        }
    };

    float acc[2][2][4];
#pragma unroll
    for (int i = 0; i < 2; ++i)
#pragma unroll
        for (int j = 0; j < 2; ++j)
#pragma unroll
            for (int q = 0; q < 4; ++q) acc[i][j][q] = 0.f;

    const int g4   = lane >> 3;
    const int g2   = g4 & 1;
    const int rowi = (lane & 7) << 4;

    stage(0, 0);
    asm volatile("cp.async.commit_group;");

    for (int c = 0; c < NCHUNK; ++c) {
        const int cur = c & 1;
        if (c + 1 < NCHUNK) {
            stage(c + 1, cur ^ 1);
            asm volatile("cp.async.commit_group;");
            asm volatile("cp.async.wait_group 1;" ::: "memory");
        } else {
            asm volatile("cp.async.wait_group 0;" ::: "memory");
        }
        __syncthreads();

        const unsigned bA0 = sbase + (unsigned)(cur * 16384);
        const unsigned bA1 = bA0 + 4096;
        const unsigned bW0 = bA0 + 8192;
        const unsigned bW1 = bA0 + 12288;

#pragma unroll
        for (int ks = 0; ks < 2; ++ks) {
            unsigned ahi[2][4], alo[2][4], bhi[2][2], blo[2][2];
#pragma unroll
            for (int mf = 0; mf < 2; ++mf) {
                int mi = wm * 4 + mf * 2;
                unsigned ti  = (unsigned)((mi + (g4 & 1)) * 4 + (ks << 1) + (g4 >> 1));
                unsigned off = ti * 128u + rowi;
                ldsm_x4(ahi[mf][0], ahi[mf][1], ahi[mf][2], ahi[mf][3], bA0 + off);
                ldsm_x4(alo[mf][0], alo[mf][1], alo[mf][2], alo[mf][3], bA1 + off);
            }
#pragma unroll
            for (int nf = 0; nf < 2; ++nf) {
                int ni = wn * 2 + nf;
                unsigned ti  = (unsigned)(ni * 4 + (ks << 1) + g2);
                unsigned off = ti * 128u + rowi;
                ldsm_x2(bhi[nf][0], bhi[nf][1], bW0 + off);
                ldsm_x2(blo[nf][0], blo[nf][1], bW1 + off);
            }
#pragma unroll
            for (int mf = 0; mf < 2; ++mf)
#pragma unroll
                for (int nf = 0; nf < 2; ++nf) {
                    mma16816(acc[mf][nf], ahi[mf], bhi[nf]);
                    mma16816(acc[mf][nf], ahi[mf], blo[nf]);
                    mma16816(acc[mf][nf], alo[mf], bhi[nf]);
                }
        }
        __syncthreads();
    }

#pragma unroll
    for (int nf = 0; nf < 2; ++nf) {
        int bcol = n0 + wn * 16 + nf * 8 + ((lane & 3) << 1);
        float2 bv = *(const float2*)&bias[bcol];
#pragma unroll
        for (int mf = 0; mf < 2; ++mf) {
            long r0 = (long)(y << 6) + wm * 32 + mf * 16 + (lane >> 2);
            float2 o0 = make_float2(acc[mf][nf][0] + bv.x, acc[mf][nf][1] + bv.y);
            float2 o1 = make_float2(acc[mf][nf][2] + bv.x, acc[mf][nf][3] + bv.y);
            *(float2*)&g_U[r0 * N + bcol]       = o0;
            *(float2*)&g_U[(r0 + 8) * N + bcol] = o1;
        }
    }
}

// ---------------------------------------------------------------------------
// Persistent recurrence kernel v11 (R13, measured best) — tensor cores,
// direct-from-global A fragments, Wh B-fragments in registers, U prefetch in
// barrier window, per-bgroup barriers with fused release-atomic.
// ---------------------------------------------------------------------------
#define PSTRIDE 34
#define RECUR_SMEM (16384 * 2 * 2 + 16 * 16 * PSTRIDE * 4)

__global__ void __launch_bounds__(512, 1) recur_k(const float* __restrict__ Wh,
                                                  const float* __restrict__ bh) {
    extern __shared__ char smraw[];
    __nv_bfloat16* hsH = (__nv_bfloat16*)smraw;          // setup temp only
    float* part = (float*)(smraw + 65536);               // [16][16][PSTRIDE]

    const int tid = threadIdx.x;
    const int w   = tid >> 5;            // warp 0..15 -> k slice [w*64, +64)
    const int l   = tid & 31;
    const int cb  = blockIdx.x;
    const int j0  = (cb & 31) << 5;
    const int bg  = cb >> 5;
    const int b0  = bg << 4;
    const int j   = j0 + l;
    unsigned* bar = &g_bar4[bg << 5];    // this group's padded counter

    const unsigned baseW = (unsigned)__cvta_generic_to_shared(hsH);

    // ---- setup: Wh -> split-bf16 B fragments in registers (two passes) ----
    unsigned Bhi[4][4][2], Blo[4][4][2];
    {
        __nv_bfloat16* wtmp = hsH;
#pragma unroll 1
        for (int pass = 0; pass < 2; ++pass) {
#pragma unroll 1
            for (int it = 0; it < 16; ++it) {
                int e  = tid + (it << 9);
                int jj = e >> 8;
                int k  = (e & 255) << 2;
                float4 f = *(const float4*)&Wh[(long)(j0 + jj) * H_ + k];
                __nv_bfloat162 p01, p23;
                if (pass == 0) {
                    p01 = __float22bfloat162_rn(make_float2(f.x, f.y));
                    p23 = __float22bfloat162_rn(make_float2(f.z, f.w));
                } else {
                    __nv_bfloat162 h01 = __float22bfloat162_rn(make_float2(f.x, f.y));
                    __nv_bfloat162 h23 = __float22bfloat162_rn(make_float2(f.z, f.w));
                    p01 = __float22bfloat162_rn(make_float2(
                        f.x - __bfloat162float(h01.x), f.y - __bfloat162float(h01.y)));
                    p23 = __float22bfloat162_rn(make_float2(
                        f.z - __bfloat162float(h23.x), f.w - __bfloat162float(h23.y)));
                }
                int off = ((jj >> 3) * 128 + (k >> 3)) * 64 + ((jj & 7) << 3) + (k & 7);
                *(__nv_bfloat162*)(wtmp + off)     = p01;
                *(__nv_bfloat162*)(wtmp + off + 2) = p23;
            }
            __syncthreads();
#pragma unroll
            for (int s = 0; s < 4; ++s) {
                int kt0 = (w << 3) + (s << 1);
#pragma unroll
                for (int nt = 0; nt < 4; ++nt) {
                    unsigned addr = baseW +
                        (unsigned)(((nt * 128 + kt0 + ((l >> 3) & 1)) << 7) + ((l & 7) << 4));
                    if (pass == 0) ldsm_x2(Bhi[s][nt][0], Bhi[s][nt][1], addr);
                    else           ldsm_x2(Blo[s][nt][0], Blo[s][nt][1], addr);
                }
            }
            __syncthreads();
        }
    }

    const int rb = tid >> 5;
    const int gb = b0 + rb;
    const float bhj = bh[j];
    const int inner = ((l >> 2) << 4) + ((l & 3) << 2);   // frag byte in tile

    // U prefetch for step 0
    float u_next = g_U[(long)(0 * 64 + gb) * H_ + j];

    for (int m = 0; m < S_; ++m) {
        const char* hH = (const char*)(g_hbf[m & 1][0] + (bg << 14));
        const char* hL = (const char*)(g_hbf[m & 1][1] + (bg << 14));

        auto loadfrag = [&](int s, unsigned* aH, unsigned* aL) {
            int kt = (w << 3) + (s << 1);
            int o00 = (kt << 7) + inner;      // bt0, kt
            int o10 = o00 + 16384;            // bt1, kt
            aH[0] = ldcg(hH + o00); aH[1] = ldcg(hH + o10);
            aH[2] = ldcg(hH + o00 + 128); aH[3] = ldcg(hH + o10 + 128);
            aL[0] = ldcg(hL + o00); aL[1] = ldcg(hL + o10);
            aL[2] = ldcg(hL + o00 + 128); aL[3] = ldcg(hL + o10 + 128);
        };

        const float u0 = u_next;   // valid when m <= S_-2

        float acc[4][4];
#pragma unroll
        for (int nt = 0; nt < 4; ++nt)
#pragma unroll
            for (int q = 0; q < 4; ++q) acc[nt][q] = 0.f;

        unsigned aH[2][4], aL[2][4];
        loadfrag(0, aH[0], aL[0]);
#pragma unroll
        for (int s = 0; s < 4; ++s) {
            const int cur = s & 1;
            if (s < 3) loadfrag(s + 1, aH[cur ^ 1], aL[cur ^ 1]);
#pragma unroll
            for (int nt = 0; nt < 4; ++nt) {
                mma16816(acc[nt], aH[cur], Bhi[s][nt]);
                mma16816(acc[nt], aH[cur], Blo[s][nt]);
                mma16816(acc[nt], aL[cur], Bhi[s][nt]);
            }
        }

        // ---- store partials (padded stride -> conflict-free) ----
        {
            float* pw = part + w * (16 * PSTRIDE);
            int prow = l >> 2, pcol = (l & 3) << 1;
#pragma unroll
            for (int nt = 0; nt < 4; ++nt) {
                *(float2*)&pw[prow * PSTRIDE + nt * 8 + pcol] =
                    make_float2(acc[nt][0], acc[nt][1]);
                *(float2*)&pw[(prow + 8) * PSTRIDE + nt * 8 + pcol] =
                    make_float2(acc[nt][2], acc[nt][3]);
            }
        }
        __syncthreads();

        // ---- reduce 16 k-slices, bias, tanh, h write (bf16 hi/lo) ----
        float av;
        {
            float s = 0.f;
#pragma unroll
            for (int ww = 0; ww < 16; ++ww)
                s += part[ww * (16 * PSTRIDE) + rb * PSTRIDE + l];
            av = s + bhj;
            if (m <= S_ - 2) {
                float hv = tanhf(u0 + av);
                __nv_bfloat16 hi = __float2bfloat16(hv);
                __nv_bfloat16 lo = __float2bfloat16(hv - __bfloat162float(hi));
                int idx = HTILE_IDX(gb, j);
                g_hbf[(m + 1) & 1][0][idx] = hi;
                g_hbf[(m + 1) & 1][1][idx] = lo;
                if (m == S_ - 2) g_ht[gb * H_ + j] = hv;
            }
        }

        // z write target (tiled bf16, rows r = b*512 + t)
        const int zr = (gb << 9) + m;
        const long zt = ((long)(zr >> 3) * 128 + (j >> 3)) * 64
                      + ((zr & 7) << 3) + (j & 7);

        if (m != S_ - 1) {
            __syncthreads();
            if (tid == 0) {
                asm volatile("red.release.gpu.global.add.u32 [%0], %1;"
                             :: "l"(bar), "r"(1u) : "memory");
            }
            // barrier window: z tanh + bf16 store AND next-step U prefetch
            if (m >= 1) {
                float zv = tanhf(av);
                __nv_bfloat16 zh = __float2bfloat16(zv);
                g_zhi[zt] = zh;
                g_zlo[zt] = __float2bfloat16(zv - __bfloat162float(zh));
            }
            if (m + 1 <= S_ - 2)
                u_next = g_U[((long)(m + 1) * 64 + gb) * H_ + j];
            if (tid == 0) {
                unsigned target = (unsigned)(32 * (m + 1));
                unsigned v;
                do {
                    asm volatile("ld.acquire.gpu.global.u32 %0, [%1];"
                                 : "=r"(v) : "l"(bar));
                } while (v < target);
            }
            __syncthreads();
        } else {
            float zv = tanhf(av);
            __nv_bfloat16 zh = __float2bfloat16(zv);
            g_zhi[zt] = zh;
            g_zlo[zt] = __float2bfloat16(zv - __bfloat162float(zh));
        }
    }
}

// ---------------------------------------------------------------------------
// Row softmax over O_=512 cols; warp per row, logits read from g_U (reused).
// ---------------------------------------------------------------------------
__global__ __launch_bounds__(256) void softmax_k(float* __restrict__ out) {
    int r = blockIdx.x * 8 + (threadIdx.x >> 5);
    int l = threadIdx.x & 31;
    const float* row = g_U + (long)r * O_;

    float4 v[4];
    float mx = -3.0e38f;
#pragma unroll
    for (int q = 0; q < 4; ++q) {
        v[q] = *(const float4*)&row[(l + (q << 5)) << 2];
        mx = fmaxf(mx, fmaxf(fmaxf(v[q].x, v[q].y), fmaxf(v[q].z, v[q].w)));
    }
#pragma unroll
    for (int o = 16; o; o >>= 1) mx = fmaxf(mx, __shfl_xor_sync(~0u, mx, o));

    float s = 0.f;
#pragma unroll
    for (int q = 0; q < 4; ++q) {
        v[q].x = expf(v[q].x - mx); v[q].y = expf(v[q].y - mx);
        v[q].z = expf(v[q].z - mx); v[q].w = expf(v[q].w - mx);
        s += (v[q].x + v[q].y) + (v[q].z + v[q].w);
    }
#pragma unroll
    for (int o = 16; o; o >>= 1) s += __shfl_xor_sync(~0u, s, o);
    float inv = 1.0f / s;

#pragma unroll
    for (int q = 0; q < 4; ++q) {
        float4 wv = make_float4(v[q].x * inv, v[q].y * inv, v[q].z * inv, v[q].w * inv);
        *(float4*)&out[(long)r * O_ + ((l + (q << 5)) << 2)] = wv;
    }
}

__global__ void copyht_k(float* __restrict__ dst) {
    int i = blockIdx.x * blockDim.x + threadIdx.x;
    if (i < B_ * H_) dst[i] = g_ht[i];
}

// ---------------------------------------------------------------------------
// Launch (only harness pointers cross the host/device boundary)
// ---------------------------------------------------------------------------
extern "C" void kernel_launch(void* const* d_in, const int* in_sizes, int n_in,
                              void* d_out, int out_size) {
    const float* x  = (const float*)d_in[0];
    const float* h0 = (const float*)d_in[1];
    const float* Wi = (const float*)d_in[2];
    const float* bi = (const float*)d_in[3];
    const float* Wh = (const float*)d_in[4];
    const float* bh = (const float*)d_in[5];
    const float* W3 = (const float*)d_in[6];
    const float* b3 = (const float*)d_in[7];
    float* out = (float*)d_out;

    cudaFuncSetAttribute(recur_k, cudaFuncAttributeMaxDynamicSharedMemorySize,
                         RECUR_SMEM);

    // 1. fused prep: init state + all operand conversions in ONE launch
    prep_k<<<(PREP_TOTAL + 255) / 256, 256>>>(x, Wi, W3, h0);

    // 2. U[t][b][:] = x[b][t][:] @ Wi^T + bi   (t = 0..510)
    gemm_bf<0><<<dim3(H_ / 64, S_ - 1), 256>>>(bi);

    // 3. Serial recurrence (persistent, 128 CTAs, 512 steps, tensor cores)
    recur_k<<<128, 512, RECUR_SMEM>>>(Wh, bh);

    // 4. logits = Z @ W3^T + b3   (g_U reused as logits buffer)
    gemm_bf<1><<<dim3(O_ / 64, (B_ * S_) / 64), 256>>>(b3);

    // 5. softmax -> d_out
    softmax_k<<<(B_ * S_) / 8, 256>>>(out);

    // 6. final hidden state appended after softmax output
    if (out_size >= B_ * S_ * O_ + B_ * H_) {
        copyht_k<<<(B_ * H_ + 255) / 256, 256>>>(out + (long)B_ * S_ * O_);
    }
}